// round 5
// baseline (speedup 1.0000x reference)
#include <cuda_runtime.h>
#include <cuda_bf16.h>
#include <math.h>

#define DD   512
#define SS   2048
#define BB   2
#define HH   8
#define GG   4
#define NROW (BB*SS)     // 4096
#define SR   72          // bf16 smem row stride (144B: conflict-free ldmatrix)

typedef unsigned int u32;

// ---- scratch (device globals; no allocation allowed) ----
__device__ __nv_bfloat16 g_xh[NROW*DD], g_xl[NROW*DD];
__device__ __nv_bfloat16 g_wh[6*DD*DD], g_wl[6*DD*DD];   // q1,k1,q2,k2,v,out
__device__ __nv_bfloat16 g_q1h[NROW*DD], g_q1l[NROW*DD];
__device__ __nv_bfloat16 g_q2h[NROW*DD], g_q2l[NROW*DD];
__device__ __nv_bfloat16 g_k1h[NROW*DD], g_k1l[NROW*DD];
__device__ __nv_bfloat16 g_k2h[NROW*DD], g_k2l[NROW*DD];
__device__ __nv_bfloat16 g_vth[BB*HH*64*SS], g_vtl[BB*HH*64*SS];  // [bh][hd][seq]
__device__ float g_o [NROW*DD];
__device__ __nv_bfloat16 g_oh[NROW*DD], g_ol[NROW*DD];
__device__ float g_mu  [BB*GG];
__device__ float g_rstd[BB*GG];

// ============================================================
// helpers
// ============================================================
__device__ __forceinline__ unsigned smem_u32(const void* p) {
    return (unsigned)__cvta_generic_to_shared(p);
}
__device__ __forceinline__ void ldsm4(u32& r0, u32& r1, u32& r2, u32& r3, unsigned a) {
    asm volatile("ldmatrix.sync.aligned.m8n8.x4.shared.b16 {%0,%1,%2,%3}, [%4];"
                 : "=r"(r0), "=r"(r1), "=r"(r2), "=r"(r3) : "r"(a));
}
__device__ __forceinline__ void mma_bf16(float* c, const u32* a, u32 b0, u32 b1) {
    asm volatile("mma.sync.aligned.m16n8k16.row.col.f32.bf16.bf16.f32 "
                 "{%0,%1,%2,%3},{%4,%5,%6,%7},{%8,%9},{%0,%1,%2,%3};"
                 : "+f"(c[0]), "+f"(c[1]), "+f"(c[2]), "+f"(c[3])
                 : "r"(a[0]), "r"(a[1]), "r"(a[2]), "r"(a[3]), "r"(b0), "r"(b1));
}
__device__ __forceinline__ void split1(float v, __nv_bfloat16& h, __nv_bfloat16& l) {
    h = __float2bfloat16(v);
    l = __float2bfloat16(v - __bfloat162float(h));
}
__device__ __forceinline__ void split2(float x, float y, u32& h, u32& l) {
    __nv_bfloat162 hh = __floats2bfloat162_rn(x, y);
    float2 hf = __bfloat1622float2(hh);
    __nv_bfloat162 ll = __floats2bfloat162_rn(x - hf.x, y - hf.y);
    h = *(u32*)&hh; l = *(u32*)&ll;
}
__device__ __forceinline__ float ex2(float x) {
    float y; asm("ex2.approx.ftz.f32 %0, %1;" : "=f"(y) : "f"(x)); return y;
}

// ============================================================
// Kernel 0: split x and all weights into bf16 hi/lo
// (scale 0.125*log2e folded into q1w/q2w)
// ============================================================
__global__ __launch_bounds__(256) void split_inputs_kernel(
    const float* __restrict__ x,
    const float* __restrict__ q1w, const float* __restrict__ k1w,
    const float* __restrict__ q2w, const float* __restrict__ k2w,
    const float* __restrict__ vw,  const float* __restrict__ ow)
{
    const float QS = 0.125f * 1.4426950408889634f;
    const int NX = NROW*DD/4;           // 524288 float4s of x
    const int NWEL = DD*DD/4;           // 65536 float4s per weight
    int i = blockIdx.x * 256 + threadIdx.x;
    if (i < NX) {
        float4 a = ((const float4*)x)[i];
        int e = i*4;
        split1(a.x, g_xh[e+0], g_xl[e+0]);
        split1(a.y, g_xh[e+1], g_xl[e+1]);
        split1(a.z, g_xh[e+2], g_xl[e+2]);
        split1(a.w, g_xh[e+3], g_xl[e+3]);
    } else {
        int j = i - NX;
        if (j >= 6*NWEL) return;
        int w = j / NWEL, e = j - w*NWEL;
        const float* src; float s = 1.f;
        switch (w) {
            case 0:  src = q1w; s = QS; break;
            case 1:  src = k1w; break;
            case 2:  src = q2w; s = QS; break;
            case 3:  src = k2w; break;
            case 4:  src = vw;  break;
            default: src = ow;  break;
        }
        float4 a = ((const float4*)src)[e];
        int o = w*DD*DD + e*4;
        split1(a.x*s, g_wh[o+0], g_wl[o+0]);
        split1(a.y*s, g_wh[o+1], g_wl[o+1]);
        split1(a.z*s, g_wh[o+2], g_wl[o+2]);
        split1(a.w*s, g_wh[o+3], g_wl[o+3]);
    }
}

// ============================================================
// shared bf16x3 64x64x64 tile compute (4 warps)
// ============================================================
__device__ __forceinline__ void mma_tile64(
    float (*c)[4], unsigned ah_b, unsigned al_b, unsigned bh_b, unsigned bl_b,
    int arow, int acol, int browin, int bcol)
{
    #pragma unroll
    for (int ks = 0; ks < 4; ++ks) {
        unsigned aoff = (unsigned)((arow*SR + ks*16 + acol) * 2);
        u32 aH[4], aL[4];
        ldsm4(aH[0],aH[1],aH[2],aH[3], ah_b + aoff);
        ldsm4(aL[0],aL[1],aL[2],aL[3], al_b + aoff);
        #pragma unroll
        for (int np = 0; np < 4; ++np) {
            unsigned boff = (unsigned)(((np*16 + browin)*SR + ks*16 + bcol) * 2);
            u32 bH[4], bL[4];
            ldsm4(bH[0],bH[1],bH[2],bH[3], bh_b + boff);
            ldsm4(bL[0],bL[1],bL[2],bL[3], bl_b + boff);
            mma_bf16(c[2*np],   aH, bH[0], bH[1]);
            mma_bf16(c[2*np],   aH, bL[0], bL[1]);
            mma_bf16(c[2*np],   aL, bH[0], bH[1]);
            mma_bf16(c[2*np+1], aH, bH[2], bH[3]);
            mma_bf16(c[2*np+1], aH, bL[2], bL[3]);
            mma_bf16(c[2*np+1], aL, bH[2], bH[3]);
        }
    }
}

// ============================================================
// Kernel 1: fused 5-way projection GEMM (pre-split bf16 inputs)
// grid (M/64, N/64, 5), block 128.
// ============================================================
__global__ __launch_bounds__(128) void qkv_mma_kernel(
    const float* __restrict__ k1b, const float* __restrict__ k2b)
{
    __shared__ __nv_bfloat16 Ah[64*SR], Al[64*SR], Bh[64*SR], Bl[64*SR];

    const int tid = threadIdx.x, lane = tid & 31, warp = tid >> 5;
    const int m0 = blockIdx.x * 64, n0 = blockIdx.y * 64, p = blockIdx.z;

    const __nv_bfloat16* Wh = g_wh + (size_t)p*DD*DD;
    const __nv_bfloat16* Wl = g_wl + (size_t)p*DD*DD;
    const float* bias = (p == 1) ? k1b : (p == 3) ? k2b : nullptr;

    float c[8][4] = {};

    const unsigned ah_b = smem_u32(Ah), al_b = smem_u32(Al);
    const unsigned bh_b = smem_u32(Bh), bl_b = smem_u32(Bl);
    const int arow   = warp*16 + (lane & 7) + ((lane >> 3) & 1) * 8;
    const int acol   = ((lane >> 4) << 3);
    const int browin = (lane & 7) + ((lane >> 4) << 3);
    const int bcol   = (((lane >> 3) & 1) << 3);

    for (int k0 = 0; k0 < DD; k0 += 64) {
        #pragma unroll
        for (int it = 0; it < 4; ++it) {
            int idx = tid + it*128;            // 0..511
            int row = idx >> 3, c8 = (idx & 7) << 3;
            size_t ga = (size_t)(m0+row)*DD + k0 + c8;
            size_t gb = (size_t)(n0+row)*DD + k0 + c8;
            *(uint4*)&Ah[row*SR+c8] = *(const uint4*)&g_xh[ga];
            *(uint4*)&Al[row*SR+c8] = *(const uint4*)&g_xl[ga];
            *(uint4*)&Bh[row*SR+c8] = *(const uint4*)&Wh[gb];
            *(uint4*)&Bl[row*SR+c8] = *(const uint4*)&Wl[gb];
        }
        __syncthreads();
        mma_tile64(c, ah_b, al_b, bh_b, bl_b, arow, acol, browin, bcol);
        __syncthreads();
    }

    const int gid = lane >> 2, tig = lane & 3;
    if (p == 4) {
        // V: write transposed split bf16: g_vt[(b*8+h)*64+hd][seq]
        #pragma unroll
        for (int nf = 0; nf < 8; ++nf)
            #pragma unroll
            for (int e = 0; e < 4; ++e) {
                int r = m0 + warp*16 + gid + (e >> 1) * 8;
                int n = n0 + nf*8 + tig*2 + (e & 1);
                int bb = r >> 11, seq = r & 2047;
                int hh = n >> 6,  hd  = n & 63;
                size_t o = ((size_t)((bb*HH + hh)*64 + hd))*SS + seq;
                __nv_bfloat16 hi, lo; split1(c[nf][e], hi, lo);
                g_vth[o] = hi; g_vtl[o] = lo;
            }
    } else {
        __nv_bfloat16 *oh, *ol;
        switch (p) {
            case 0:  oh = g_q1h; ol = g_q1l; break;
            case 1:  oh = g_k1h; ol = g_k1l; break;
            case 2:  oh = g_q2h; ol = g_q2l; break;
            default: oh = g_k2h; ol = g_k2l; break;
        }
        #pragma unroll
        for (int nf = 0; nf < 8; ++nf)
            #pragma unroll
            for (int hf = 0; hf < 2; ++hf) {
                int r = m0 + warp*16 + gid + hf*8;
                int n = n0 + nf*8 + tig*2;
                float b0 = bias ? bias[n]   : 0.f;
                float b1 = bias ? bias[n+1] : 0.f;
                u32 h, l; split2(c[nf][2*hf] + b0, c[nf][2*hf+1] + b1, h, l);
                *(u32*)&oh[(size_t)r*DD + n] = h;
                *(u32*)&ol[(size_t)r*DD + n] = l;
            }
    }
}

// ============================================================
// Kernel 2: dual-stream flash attention (bf16x3, shared V frags)
// grid (S/64, B*H), block 128 (4 warps). base-2 softmax.
// ============================================================
__device__ __forceinline__ void softmax_update(
    float (*c)[4], float* m, float* l, float (*o)[4])
{
    #pragma unroll
    for (int hf = 0; hf < 2; ++hf) {
        float mx = -1e30f;
        #pragma unroll
        for (int nf = 0; nf < 8; ++nf)
            mx = fmaxf(mx, fmaxf(c[nf][2*hf], c[nf][2*hf+1]));
        mx = fmaxf(mx, __shfl_xor_sync(0xffffffffu, mx, 1));
        mx = fmaxf(mx, __shfl_xor_sync(0xffffffffu, mx, 2));
        float mn   = fmaxf(m[hf], mx);
        float corr = ex2(m[hf] - mn);
        float rs = 0.f;
        #pragma unroll
        for (int nf = 0; nf < 8; ++nf) {
            float p0 = ex2(c[nf][2*hf]   - mn);
            float p1 = ex2(c[nf][2*hf+1] - mn);
            c[nf][2*hf] = p0; c[nf][2*hf+1] = p1;
            rs += p0 + p1;
        }
        rs += __shfl_xor_sync(0xffffffffu, rs, 1);
        rs += __shfl_xor_sync(0xffffffffu, rs, 2);
        l[hf] = l[hf]*corr + rs;
        m[hf] = mn;
        #pragma unroll
        for (int nf = 0; nf < 8; ++nf) {
            o[nf][2*hf]   *= corr;
            o[nf][2*hf+1] *= corr;
        }
    }
}

__global__ __launch_bounds__(128) void attn_mma_kernel(
    const float* __restrict__ lq1, const float* __restrict__ lk1,
    const float* __restrict__ lq2, const float* __restrict__ lk2)
{
    extern __shared__ __nv_bfloat16 sm[];
    __nv_bfloat16* q1h = sm;
    __nv_bfloat16* q1l = q1h + 64*SR;
    __nv_bfloat16* q2h = q1l + 64*SR;
    __nv_bfloat16* q2l = q2h + 64*SR;
    __nv_bfloat16* k1h = q2l + 64*SR;
    __nv_bfloat16* k1l = k1h + 64*SR;
    __nv_bfloat16* k2h = k1l + 64*SR;
    __nv_bfloat16* k2l = k2h + 64*SR;
    __nv_bfloat16* vh  = k2l + 64*SR;
    __nv_bfloat16* vl  = vh  + 64*SR;

    const int tid = threadIdx.x, lane = tid & 31, warp = tid >> 5;
    const int bh = blockIdx.y, b = bh >> 3, h = bh & 7;
    const int q0 = blockIdx.x * 64;

    {
        const size_t gbase = (size_t)(b*SS + q0)*DD + h*64;
        #pragma unroll
        for (int it = 0; it < 4; ++it) {
            int idx = tid + it*128;
            int row = idx >> 3, c8 = (idx & 7) << 3;
            size_t go = gbase + (size_t)row*DD + c8;
            *(uint4*)&q1h[row*SR+c8] = *(const uint4*)&g_q1h[go];
            *(uint4*)&q1l[row*SR+c8] = *(const uint4*)&g_q1l[go];
            *(uint4*)&q2h[row*SR+c8] = *(const uint4*)&g_q2h[go];
            *(uint4*)&q2l[row*SR+c8] = *(const uint4*)&g_q2l[go];
        }
    }

    float o1[8][4] = {}, o2[8][4] = {};
    float m1[2] = {-1e30f, -1e30f}, l1[2] = {0.f, 0.f};
    float m2[2] = {-1e30f, -1e30f}, l2[2] = {0.f, 0.f};

    const unsigned q1h_b = smem_u32(q1h), q1l_b = smem_u32(q1l);
    const unsigned q2h_b = smem_u32(q2h), q2l_b = smem_u32(q2l);
    const unsigned k1h_b = smem_u32(k1h), k1l_b = smem_u32(k1l);
    const unsigned k2h_b = smem_u32(k2h), k2l_b = smem_u32(k2l);
    const unsigned vh_b  = smem_u32(vh),  vl_b  = smem_u32(vl);

    const int arow   = warp*16 + (lane & 7) + ((lane >> 3) & 1) * 8;
    const int acol   = ((lane >> 4) << 3);
    const int browin = (lane & 7) + ((lane >> 4) << 3);
    const int bcol   = (((lane >> 3) & 1) << 3);

    for (int kc = 0; kc < SS; kc += 64) {
        const size_t kb = (size_t)(b*SS + kc)*DD + h*64;
        const size_t vb = (size_t)(bh*64)*SS + kc;
        #pragma unroll
        for (int it = 0; it < 4; ++it) {
            int idx = tid + it*128;
            int row = idx >> 3, c8 = (idx & 7) << 3;
            size_t go = kb + (size_t)row*DD + c8;
            *(uint4*)&k1h[row*SR+c8] = *(const uint4*)&g_k1h[go];
            *(uint4*)&k1l[row*SR+c8] = *(const uint4*)&g_k1l[go];
            *(uint4*)&k2h[row*SR+c8] = *(const uint4*)&g_k2h[go];
            *(uint4*)&k2l[row*SR+c8] = *(const uint4*)&g_k2l[go];
            size_t gv = vb + (size_t)row*SS + c8;
            *(uint4*)&vh[row*SR+c8] = *(const uint4*)&g_vth[gv];
            *(uint4*)&vl[row*SR+c8] = *(const uint4*)&g_vtl[gv];
        }
        __syncthreads();

        // S tiles for both streams
        float c1[8][4] = {}, c2[8][4] = {};
        mma_tile64(c1, q1h_b, q1l_b, k1h_b, k1l_b, arow, acol, browin, bcol);
        softmax_update(c1, m1, l1, o1);
        mma_tile64(c2, q2h_b, q2l_b, k2h_b, k2l_b, arow, acol, browin, bcol);
        softmax_update(c2, m2, l2, o2);

        // shared PV: load V fragments once, feed both streams
        #pragma unroll
        for (int ks = 0; ks < 4; ++ks) {
            u32 p1H[4], p1L[4], p2H[4], p2L[4];
            split2(c1[2*ks][0],   c1[2*ks][1],   p1H[0], p1L[0]);
            split2(c1[2*ks][2],   c1[2*ks][3],   p1H[1], p1L[1]);
            split2(c1[2*ks+1][0], c1[2*ks+1][1], p1H[2], p1L[2]);
            split2(c1[2*ks+1][2], c1[2*ks+1][3], p1H[3], p1L[3]);
            split2(c2[2*ks][0],   c2[2*ks][1],   p2H[0], p2L[0]);
            split2(c2[2*ks][2],   c2[2*ks][3],   p2H[1], p2L[1]);
            split2(c2[2*ks+1][0], c2[2*ks+1][1], p2H[2], p2L[2]);
            split2(c2[2*ks+1][2], c2[2*ks+1][3], p2H[3], p2L[3]);
            #pragma unroll
            for (int np = 0; np < 4; ++np) {
                unsigned boff = (unsigned)(((np*16 + browin)*SR + ks*16 + bcol) * 2);
                u32 bH[4], bL[4];
                ldsm4(bH[0],bH[1],bH[2],bH[3], vh_b + boff);
                ldsm4(bL[0],bL[1],bL[2],bL[3], vl_b + boff);
                mma_bf16(o1[2*np],   p1H, bH[0], bH[1]);
                mma_bf16(o1[2*np],   p1H, bL[0], bL[1]);
                mma_bf16(o1[2*np],   p1L, bH[0], bH[1]);
                mma_bf16(o1[2*np+1], p1H, bH[2], bH[3]);
                mma_bf16(o1[2*np+1], p1H, bL[2], bL[3]);
                mma_bf16(o1[2*np+1], p1L, bH[2], bH[3]);
                mma_bf16(o2[2*np],   p2H, bH[0], bH[1]);
                mma_bf16(o2[2*np],   p2H, bL[0], bL[1]);
                mma_bf16(o2[2*np],   p2L, bH[0], bH[1]);
                mma_bf16(o2[2*np+1], p2H, bH[2], bH[3]);
                mma_bf16(o2[2*np+1], p2H, bL[2], bL[3]);
                mma_bf16(o2[2*np+1], p2L, bH[2], bH[3]);
            }
        }
        __syncthreads();
    }

    const float lam = __expf(lq1[h]*lk1[h]) - __expf(lq2[h]*lk2[h]) + 0.2f;
    const int gid = lane >> 2, tig = lane & 3;
    const float i1[2] = {1.f/l1[0], 1.f/l1[1]};
    const float i2[2] = {lam/l2[0], lam/l2[1]};
    #pragma unroll
    for (int hf = 0; hf < 2; ++hf)
        #pragma unroll
        for (int nf = 0; nf < 8; ++nf) {
            int r = q0 + warp*16 + gid + hf*8;
            int col = h*64 + nf*8 + tig*2;
            float2 y;
            y.x = o1[nf][2*hf]  *i1[hf] - o2[nf][2*hf]  *i2[hf];
            y.y = o1[nf][2*hf+1]*i1[hf] - o2[nf][2*hf+1]*i2[hf];
            *(float2*)&g_o[(size_t)(b*SS + r)*DD + col] = y;
        }
}

// ============================================================
// Kernel 3: GroupNorm stats
// ============================================================
__global__ __launch_bounds__(256) void gn_stats_kernel()
{
    const int gi = blockIdx.x;
    const int b = gi >> 2, g = gi & 3;
    const int tid = threadIdx.x;
    const float* base = g_o + (size_t)b*SS*DD + g*128;

    float s = 0.f, ss = 0.f;
    for (int i = tid; i < SS*128; i += 256) {
        int r = i >> 7, c = i & 127;
        float v = base[(size_t)r*DD + c];
        s += v; ss += v*v;
    }
    __shared__ float rs[256], rq[256];
    rs[tid] = s; rq[tid] = ss;
    __syncthreads();
    for (int off = 128; off > 0; off >>= 1) {
        if (tid < off) { rs[tid] += rs[tid+off]; rq[tid] += rq[tid+off]; }
        __syncthreads();
    }
    if (tid == 0) {
        const float n = (float)(SS*128);
        float mu  = rs[0] / n;
        float var = rq[0] / n - mu*mu;
        g_mu[gi]   = mu;
        g_rstd[gi] = rsqrtf(var + 1e-5f);
    }
}

// ============================================================
// Kernel 3b: apply GroupNorm and split to bf16 hi/lo
// ============================================================
__global__ __launch_bounds__(256) void gn_apply_kernel(
    const float* __restrict__ gw, const float* __restrict__ gb)
{
    int i = (blockIdx.x * 256 + threadIdx.x) * 4;
    if (i >= NROW*DD) return;
    int row = i >> 9, col = i & 511;
    int gi = (row >> 11)*4 + (col >> 7);
    float mu = g_mu[gi], rst = g_rstd[gi];
    float4 a = *(const float4*)&g_o[i];
    float4 w = *(const float4*)&gw[col];
    float4 s = *(const float4*)&gb[col];
    split1((a.x - mu)*rst*w.x + s.x, g_oh[i+0], g_ol[i+0]);
    split1((a.y - mu)*rst*w.y + s.y, g_oh[i+1], g_ol[i+1]);
    split1((a.z - mu)*rst*w.z + s.z, g_oh[i+2], g_ol[i+2]);
    split1((a.w - mu)*rst*w.w + s.w, g_oh[i+3], g_ol[i+3]);
}

// ============================================================
// Kernel 4: output GEMM (bf16x3 mma), y = norm(o) @ out_w^T + b
// ============================================================
__global__ __launch_bounds__(128) void out_mma_kernel(
    const float* __restrict__ bias, float* __restrict__ y)
{
    __shared__ __nv_bfloat16 Ah[64*SR], Al[64*SR], Bh[64*SR], Bl[64*SR];

    const int tid = threadIdx.x, lane = tid & 31, warp = tid >> 5;
    const int m0 = blockIdx.x * 64, n0 = blockIdx.y * 64;

    const __nv_bfloat16* Wh = g_wh + (size_t)5*DD*DD;
    const __nv_bfloat16* Wl = g_wl + (size_t)5*DD*DD;

    float c[8][4] = {};

    const unsigned ah_b = smem_u32(Ah), al_b = smem_u32(Al);
    const unsigned bh_b = smem_u32(Bh), bl_b = smem_u32(Bl);
    const int arow   = warp*16 + (lane & 7) + ((lane >> 3) & 1) * 8;
    const int acol   = ((lane >> 4) << 3);
    const int browin = (lane & 7) + ((lane >> 4) << 3);
    const int bcol   = (((lane >> 3) & 1) << 3);

    for (int k0 = 0; k0 < DD; k0 += 64) {
        #pragma unroll
        for (int it = 0; it < 4; ++it) {
            int idx = tid + it*128;
            int row = idx >> 3, c8 = (idx & 7) << 3;
            size_t ga = (size_t)(m0+row)*DD + k0 + c8;
            size_t gb = (size_t)(n0+row)*DD + k0 + c8;
            *(uint4*)&Ah[row*SR+c8] = *(const uint4*)&g_oh[ga];
            *(uint4*)&Al[row*SR+c8] = *(const uint4*)&g_ol[ga];
            *(uint4*)&Bh[row*SR+c8] = *(const uint4*)&Wh[gb];
            *(uint4*)&Bl[row*SR+c8] = *(const uint4*)&Wl[gb];
        }
        __syncthreads();
        mma_tile64(c, ah_b, al_b, bh_b, bl_b, arow, acol, browin, bcol);
        __syncthreads();
    }

    const int gid = lane >> 2, tig = lane & 3;
    #pragma unroll
    for (int nf = 0; nf < 8; ++nf)
        #pragma unroll
        for (int hf = 0; hf < 2; ++hf) {
            int r = m0 + warp*16 + gid + hf*8;
            int n = n0 + nf*8 + tig*2;
            float2 o;
            o.x = c[nf][2*hf]   + bias[n];
            o.y = c[nf][2*hf+1] + bias[n+1];
            *(float2*)&y[(size_t)r*DD + n] = o;
        }
}

// ============================================================
// launch
// ============================================================
extern "C" void kernel_launch(void* const* d_in, const int* in_sizes, int n_in,
                              void* d_out, int out_size)
{
    const float* x   = (const float*)d_in[0];
    const float* K1w = (const float*)d_in[1];
    const float* K1b = (const float*)d_in[2];
    const float* Q1w = (const float*)d_in[3];
    const float* K2w = (const float*)d_in[4];
    const float* K2b = (const float*)d_in[5];
    const float* Q2w = (const float*)d_in[6];
    const float* Vw  = (const float*)d_in[7];
    const float* lq1 = (const float*)d_in[8];
    const float* lk1 = (const float*)d_in[9];
    const float* lq2 = (const float*)d_in[10];
    const float* lk2 = (const float*)d_in[11];
    const float* gw  = (const float*)d_in[12];
    const float* gb  = (const float*)d_in[13];
    const float* Ow  = (const float*)d_in[14];
    const float* Ob  = (const float*)d_in[15];
    float* y = (float*)d_out;

    const int ATT_SMEM = 10 * 64 * SR * (int)sizeof(__nv_bfloat16);  // 92160 B
    cudaFuncSetAttribute(attn_mma_kernel,
                         cudaFuncAttributeMaxDynamicSharedMemorySize, ATT_SMEM);

    const int NSPLIT = (NROW*DD/4 + 6*DD*DD/4 + 255) / 256;
    split_inputs_kernel<<<NSPLIT, 256>>>(x, Q1w, K1w, Q2w, K2w, Vw, Ow);
    qkv_mma_kernel<<<dim3(NROW/64, DD/64, 5), 128>>>(K1b, K2b);
    attn_mma_kernel<<<dim3(SS/64, BB*HH), 128, ATT_SMEM>>>(lq1, lk1, lq2, lk2);
    gn_stats_kernel<<<BB*GG, 256>>>();
    gn_apply_kernel<<<NROW*DD/4/256, 256>>>(gw, gb);
    out_mma_kernel<<<dim3(NROW/64, DD/64), 128>>>(Ob, y);
}

// round 8
// speedup vs baseline: 2.0839x; 2.0839x over previous
#include <cuda_runtime.h>
#include <cuda_bf16.h>
#include <math.h>

#define DD   512
#define SS   2048
#define BB   2
#define HH   8
#define GG   4
#define NROW (BB*SS)     // 4096
#define SR   72          // bf16 smem row stride (144B: conflict-free ldmatrix)

typedef unsigned int u32;

// ---- scratch (device globals; no allocation allowed) ----
__device__ __nv_bfloat16 g_xh[NROW*DD], g_xl[NROW*DD];
__device__ __nv_bfloat16 g_wh[6*DD*DD], g_wl[6*DD*DD];   // q1,k1,q2,k2,v,out
__device__ __nv_bfloat16 g_q1h[NROW*DD], g_q1l[NROW*DD];
__device__ __nv_bfloat16 g_q2h[NROW*DD], g_q2l[NROW*DD];
__device__ __nv_bfloat16 g_k1h[NROW*DD], g_k1l[NROW*DD];
__device__ __nv_bfloat16 g_k2h[NROW*DD], g_k2l[NROW*DD];
__device__ __nv_bfloat16 g_vth[BB*HH*64*SS], g_vtl[BB*HH*64*SS];  // [bh][hd][seq]
__device__ float g_o [NROW*DD];
__device__ __nv_bfloat16 g_oh[NROW*DD], g_ol[NROW*DD];
__device__ float g_part_s[BB*GG*32], g_part_q[BB*GG*32];
__device__ float g_mu  [BB*GG];
__device__ float g_rstd[BB*GG];

// ============================================================
// helpers
// ============================================================
__device__ __forceinline__ unsigned smem_u32(const void* p) {
    return (unsigned)__cvta_generic_to_shared(p);
}
__device__ __forceinline__ void ldsm4(u32& r0, u32& r1, u32& r2, u32& r3, unsigned a) {
    asm volatile("ldmatrix.sync.aligned.m8n8.x4.shared.b16 {%0,%1,%2,%3}, [%4];"
                 : "=r"(r0), "=r"(r1), "=r"(r2), "=r"(r3) : "r"(a));
}
__device__ __forceinline__ void mma_bf16(float* c, const u32* a, u32 b0, u32 b1) {
    asm volatile("mma.sync.aligned.m16n8k16.row.col.f32.bf16.bf16.f32 "
                 "{%0,%1,%2,%3},{%4,%5,%6,%7},{%8,%9},{%0,%1,%2,%3};"
                 : "+f"(c[0]), "+f"(c[1]), "+f"(c[2]), "+f"(c[3])
                 : "r"(a[0]), "r"(a[1]), "r"(a[2]), "r"(a[3]), "r"(b0), "r"(b1));
}
__device__ __forceinline__ void split1(float v, __nv_bfloat16& h, __nv_bfloat16& l) {
    h = __float2bfloat16(v);
    l = __float2bfloat16(v - __bfloat162float(h));
}
__device__ __forceinline__ void split2(float x, float y, u32& h, u32& l) {
    __nv_bfloat162 hh = __floats2bfloat162_rn(x, y);
    float2 hf = __bfloat1622float2(hh);
    __nv_bfloat162 ll = __floats2bfloat162_rn(x - hf.x, y - hf.y);
    h = *(u32*)&hh; l = *(u32*)&ll;
}
__device__ __forceinline__ float ex2(float x) {
    float y; asm("ex2.approx.ftz.f32 %0, %1;" : "=f"(y) : "f"(x)); return y;
}

// ============================================================
// Kernel 0: split x and all weights into bf16 hi/lo
// (scale 0.125*log2e folded into q1w/q2w)
// ============================================================
__global__ __launch_bounds__(256) void split_inputs_kernel(
    const float* __restrict__ x,
    const float* __restrict__ q1w, const float* __restrict__ k1w,
    const float* __restrict__ q2w, const float* __restrict__ k2w,
    const float* __restrict__ vw,  const float* __restrict__ ow)
{
    const float QS = 0.125f * 1.4426950408889634f;
    const int NX = NROW*DD/4;
    const int NWEL = DD*DD/4;
    int i = blockIdx.x * 256 + threadIdx.x;
    if (i < NX) {
        float4 a = ((const float4*)x)[i];
        int e = i*4;
        split1(a.x, g_xh[e+0], g_xl[e+0]);
        split1(a.y, g_xh[e+1], g_xl[e+1]);
        split1(a.z, g_xh[e+2], g_xl[e+2]);
        split1(a.w, g_xh[e+3], g_xl[e+3]);
    } else {
        int j = i - NX;
        if (j >= 6*NWEL) return;
        int w = j / NWEL, e = j - w*NWEL;
        const float* src; float s = 1.f;
        switch (w) {
            case 0:  src = q1w; s = QS; break;
            case 1:  src = k1w; break;
            case 2:  src = q2w; s = QS; break;
            case 3:  src = k2w; break;
            case 4:  src = vw;  break;
            default: src = ow;  break;
        }
        float4 a = ((const float4*)src)[e];
        int o = w*DD*DD + e*4;
        split1(a.x*s, g_wh[o+0], g_wl[o+0]);
        split1(a.y*s, g_wh[o+1], g_wl[o+1]);
        split1(a.z*s, g_wh[o+2], g_wl[o+2]);
        split1(a.w*s, g_wh[o+3], g_wl[o+3]);
    }
}

// ============================================================
// shared bf16x3 64x64x64 tile compute (4 warps)
// ============================================================
__device__ __forceinline__ void mma_tile64(
    float (*c)[4], unsigned ah_b, unsigned al_b, unsigned bh_b, unsigned bl_b,
    int arow, int acol, int browin, int bcol)
{
    #pragma unroll
    for (int ks = 0; ks < 4; ++ks) {
        unsigned aoff = (unsigned)((arow*SR + ks*16 + acol) * 2);
        u32 aH[4], aL[4];
        ldsm4(aH[0],aH[1],aH[2],aH[3], ah_b + aoff);
        ldsm4(aL[0],aL[1],aL[2],aL[3], al_b + aoff);
        #pragma unroll
        for (int np = 0; np < 4; ++np) {
            unsigned boff = (unsigned)(((np*16 + browin)*SR + ks*16 + bcol) * 2);
            u32 bH[4], bL[4];
            ldsm4(bH[0],bH[1],bH[2],bH[3], bh_b + boff);
            ldsm4(bL[0],bL[1],bL[2],bL[3], bl_b + boff);
            mma_bf16(c[2*np],   aH, bH[0], bH[1]);
            mma_bf16(c[2*np],   aH, bL[0], bL[1]);
            mma_bf16(c[2*np],   aL, bH[0], bH[1]);
            mma_bf16(c[2*np+1], aH, bH[2], bH[3]);
            mma_bf16(c[2*np+1], aH, bL[2], bL[3]);
            mma_bf16(c[2*np+1], aL, bH[2], bH[3]);
        }
    }
}

// ============================================================
// Kernel 1: fused 5-way projection GEMM (pre-split bf16 inputs)
// ============================================================
__global__ __launch_bounds__(128) void qkv_mma_kernel(
    const float* __restrict__ k1b, const float* __restrict__ k2b)
{
    __shared__ __nv_bfloat16 Ah[64*SR], Al[64*SR], Bh[64*SR], Bl[64*SR];

    const int tid = threadIdx.x, lane = tid & 31, warp = tid >> 5;
    const int m0 = blockIdx.x * 64, n0 = blockIdx.y * 64, p = blockIdx.z;

    const __nv_bfloat16* Wh = g_wh + (size_t)p*DD*DD;
    const __nv_bfloat16* Wl = g_wl + (size_t)p*DD*DD;
    const float* bias = (p == 1) ? k1b : (p == 3) ? k2b : nullptr;

    float c[8][4] = {};

    const unsigned ah_b = smem_u32(Ah), al_b = smem_u32(Al);
    const unsigned bh_b = smem_u32(Bh), bl_b = smem_u32(Bl);
    const int arow   = warp*16 + (lane & 7) + ((lane >> 3) & 1) * 8;
    const int acol   = ((lane >> 4) << 3);
    const int browin = (lane & 7) + ((lane >> 4) << 3);
    const int bcol   = (((lane >> 3) & 1) << 3);

    for (int k0 = 0; k0 < DD; k0 += 64) {
        #pragma unroll
        for (int it = 0; it < 4; ++it) {
            int idx = tid + it*128;
            int row = idx >> 3, c8 = (idx & 7) << 3;
            size_t ga = (size_t)(m0+row)*DD + k0 + c8;
            size_t gb = (size_t)(n0+row)*DD + k0 + c8;
            *(uint4*)&Ah[row*SR+c8] = *(const uint4*)&g_xh[ga];
            *(uint4*)&Al[row*SR+c8] = *(const uint4*)&g_xl[ga];
            *(uint4*)&Bh[row*SR+c8] = *(const uint4*)&Wh[gb];
            *(uint4*)&Bl[row*SR+c8] = *(const uint4*)&Wl[gb];
        }
        __syncthreads();
        mma_tile64(c, ah_b, al_b, bh_b, bl_b, arow, acol, browin, bcol);
        __syncthreads();
    }

    const int gid = lane >> 2, tig = lane & 3;
    if (p == 4) {
        #pragma unroll
        for (int nf = 0; nf < 8; ++nf)
            #pragma unroll
            for (int e = 0; e < 4; ++e) {
                int r = m0 + warp*16 + gid + (e >> 1) * 8;
                int n = n0 + nf*8 + tig*2 + (e & 1);
                int bb = r >> 11, seq = r & 2047;
                int hh = n >> 6,  hd  = n & 63;
                size_t o = ((size_t)((bb*HH + hh)*64 + hd))*SS + seq;
                __nv_bfloat16 hi, lo; split1(c[nf][e], hi, lo);
                g_vth[o] = hi; g_vtl[o] = lo;
            }
    } else {
        __nv_bfloat16 *oh, *ol;
        switch (p) {
            case 0:  oh = g_q1h; ol = g_q1l; break;
            case 1:  oh = g_k1h; ol = g_k1l; break;
            case 2:  oh = g_q2h; ol = g_q2l; break;
            default: oh = g_k2h; ol = g_k2l; break;
        }
        #pragma unroll
        for (int nf = 0; nf < 8; ++nf)
            #pragma unroll
            for (int hf = 0; hf < 2; ++hf) {
                int r = m0 + warp*16 + gid + hf*8;
                int n = n0 + nf*8 + tig*2;
                float b0 = bias ? bias[n]   : 0.f;
                float b1 = bias ? bias[n+1] : 0.f;
                u32 h, l; split2(c[nf][2*hf] + b0, c[nf][2*hf+1] + b1, h, l);
                *(u32*)&oh[(size_t)r*DD + n] = h;
                *(u32*)&ol[(size_t)r*DD + n] = l;
            }
    }
}

// ============================================================
// Kernel 2: dual-stream flash attention (bf16x3)
// per-stream: S mma -> base-2 softmax -> PV mma (one S tile live)
// ============================================================
__device__ __forceinline__ void attn_stream_tc(
    unsigned qh_b, unsigned ql_b, unsigned kh_b, unsigned kl_b,
    unsigned vh_b, unsigned vl_b,
    int arow, int acol, int browin, int bcol,
    float* m, float* l, float (*o)[4])
{
    float c[8][4] = {};
    mma_tile64(c, qh_b, ql_b, kh_b, kl_b, arow, acol, browin, bcol);

    #pragma unroll
    for (int hf = 0; hf < 2; ++hf) {
        float mx = -1e30f;
        #pragma unroll
        for (int nf = 0; nf < 8; ++nf)
            mx = fmaxf(mx, fmaxf(c[nf][2*hf], c[nf][2*hf+1]));
        mx = fmaxf(mx, __shfl_xor_sync(0xffffffffu, mx, 1));
        mx = fmaxf(mx, __shfl_xor_sync(0xffffffffu, mx, 2));
        float mn   = fmaxf(m[hf], mx);
        float corr = ex2(m[hf] - mn);
        float rs = 0.f;
        #pragma unroll
        for (int nf = 0; nf < 8; ++nf) {
            float p0 = ex2(c[nf][2*hf]   - mn);
            float p1 = ex2(c[nf][2*hf+1] - mn);
            c[nf][2*hf] = p0; c[nf][2*hf+1] = p1;
            rs += p0 + p1;
        }
        rs += __shfl_xor_sync(0xffffffffu, rs, 1);
        rs += __shfl_xor_sync(0xffffffffu, rs, 2);
        l[hf] = l[hf]*corr + rs;
        m[hf] = mn;
        #pragma unroll
        for (int nf = 0; nf < 8; ++nf) {
            o[nf][2*hf]   *= corr;
            o[nf][2*hf+1] *= corr;
        }
    }

    #pragma unroll
    for (int ks = 0; ks < 4; ++ks) {
        u32 pH[4], pL[4];
        split2(c[2*ks][0],   c[2*ks][1],   pH[0], pL[0]);
        split2(c[2*ks][2],   c[2*ks][3],   pH[1], pL[1]);
        split2(c[2*ks+1][0], c[2*ks+1][1], pH[2], pL[2]);
        split2(c[2*ks+1][2], c[2*ks+1][3], pH[3], pL[3]);
        #pragma unroll
        for (int np = 0; np < 4; ++np) {
            unsigned boff = (unsigned)(((np*16 + browin)*SR + ks*16 + bcol) * 2);
            u32 bH[4], bL[4];
            ldsm4(bH[0],bH[1],bH[2],bH[3], vh_b + boff);
            ldsm4(bL[0],bL[1],bL[2],bL[3], vl_b + boff);
            mma_bf16(o[2*np],   pH, bH[0], bH[1]);
            mma_bf16(o[2*np],   pH, bL[0], bL[1]);
            mma_bf16(o[2*np],   pL, bH[0], bH[1]);
            mma_bf16(o[2*np+1], pH, bH[2], bH[3]);
            mma_bf16(o[2*np+1], pH, bL[2], bL[3]);
            mma_bf16(o[2*np+1], pL, bH[2], bH[3]);
        }
    }
}

__global__ __launch_bounds__(128) void attn_mma_kernel(
    const float* __restrict__ lq1, const float* __restrict__ lk1,
    const float* __restrict__ lq2, const float* __restrict__ lk2)
{
    extern __shared__ __nv_bfloat16 sm[];
    __nv_bfloat16* q1h = sm;
    __nv_bfloat16* q1l = q1h + 64*SR;
    __nv_bfloat16* q2h = q1l + 64*SR;
    __nv_bfloat16* q2l = q2h + 64*SR;
    __nv_bfloat16* k1h = q2l + 64*SR;
    __nv_bfloat16* k1l = k1h + 64*SR;
    __nv_bfloat16* k2h = k1l + 64*SR;
    __nv_bfloat16* k2l = k2h + 64*SR;
    __nv_bfloat16* vh  = k2l + 64*SR;
    __nv_bfloat16* vl  = vh  + 64*SR;

    const int tid = threadIdx.x, lane = tid & 31, warp = tid >> 5;
    const int bh = blockIdx.y, b = bh >> 3, h = bh & 7;
    const int q0 = blockIdx.x * 64;

    {
        const size_t gbase = (size_t)(b*SS + q0)*DD + h*64;
        #pragma unroll
        for (int it = 0; it < 4; ++it) {
            int idx = tid + it*128;
            int row = idx >> 3, c8 = (idx & 7) << 3;
            size_t go = gbase + (size_t)row*DD + c8;
            *(uint4*)&q1h[row*SR+c8] = *(const uint4*)&g_q1h[go];
            *(uint4*)&q1l[row*SR+c8] = *(const uint4*)&g_q1l[go];
            *(uint4*)&q2h[row*SR+c8] = *(const uint4*)&g_q2h[go];
            *(uint4*)&q2l[row*SR+c8] = *(const uint4*)&g_q2l[go];
        }
    }

    float o1[8][4] = {}, o2[8][4] = {};
    float m1[2] = {-1e30f, -1e30f}, l1[2] = {0.f, 0.f};
    float m2[2] = {-1e30f, -1e30f}, l2[2] = {0.f, 0.f};

    const unsigned q1h_b = smem_u32(q1h), q1l_b = smem_u32(q1l);
    const unsigned q2h_b = smem_u32(q2h), q2l_b = smem_u32(q2l);
    const unsigned k1h_b = smem_u32(k1h), k1l_b = smem_u32(k1l);
    const unsigned k2h_b = smem_u32(k2h), k2l_b = smem_u32(k2l);
    const unsigned vh_b  = smem_u32(vh),  vl_b  = smem_u32(vl);

    const int arow   = warp*16 + (lane & 7) + ((lane >> 3) & 1) * 8;
    const int acol   = ((lane >> 4) << 3);
    const int browin = (lane & 7) + ((lane >> 4) << 3);
    const int bcol   = (((lane >> 3) & 1) << 3);

    for (int kc = 0; kc < SS; kc += 64) {
        const size_t kb = (size_t)(b*SS + kc)*DD + h*64;
        const size_t vb = (size_t)(bh*64)*SS + kc;
        #pragma unroll
        for (int it = 0; it < 4; ++it) {
            int idx = tid + it*128;
            int row = idx >> 3, c8 = (idx & 7) << 3;
            size_t go = kb + (size_t)row*DD + c8;
            *(uint4*)&k1h[row*SR+c8] = *(const uint4*)&g_k1h[go];
            *(uint4*)&k1l[row*SR+c8] = *(const uint4*)&g_k1l[go];
            *(uint4*)&k2h[row*SR+c8] = *(const uint4*)&g_k2h[go];
            *(uint4*)&k2l[row*SR+c8] = *(const uint4*)&g_k2l[go];
            size_t gv = vb + (size_t)row*SS + c8;
            *(uint4*)&vh[row*SR+c8] = *(const uint4*)&g_vth[gv];
            *(uint4*)&vl[row*SR+c8] = *(const uint4*)&g_vtl[gv];
        }
        __syncthreads();
        attn_stream_tc(q1h_b, q1l_b, k1h_b, k1l_b, vh_b, vl_b,
                       arow, acol, browin, bcol, m1, l1, o1);
        attn_stream_tc(q2h_b, q2l_b, k2h_b, k2l_b, vh_b, vl_b,
                       arow, acol, browin, bcol, m2, l2, o2);
        __syncthreads();
    }

    const float lam = __expf(lq1[h]*lk1[h]) - __expf(lq2[h]*lk2[h]) + 0.2f;
    const int gid = lane >> 2, tig = lane & 3;
    const float i1[2] = {1.f/l1[0], 1.f/l1[1]};
    const float i2[2] = {lam/l2[0], lam/l2[1]};
    #pragma unroll
    for (int hf = 0; hf < 2; ++hf)
        #pragma unroll
        for (int nf = 0; nf < 8; ++nf) {
            int r = q0 + warp*16 + gid + hf*8;
            int col = h*64 + nf*8 + tig*2;
            float2 y;
            y.x = o1[nf][2*hf]  *i1[hf] - o2[nf][2*hf]  *i2[hf];
            y.y = o1[nf][2*hf+1]*i1[hf] - o2[nf][2*hf+1]*i2[hf];
            *(float2*)&g_o[(size_t)(b*SS + r)*DD + col] = y;
        }
}

// ============================================================
// Kernel 3a: GroupNorm stats stage 1 — 256 CTAs of partials
// grid (32, 8): blockIdx.y = group gi, blockIdx.x = 64-row chunk
// ============================================================
__global__ __launch_bounds__(256) void gn_stats1_kernel()
{
    const int gi = blockIdx.y;           // 0..7
    const int b = gi >> 2, g = gi & 3;
    const int r0 = blockIdx.x * 64;
    const int tid = threadIdx.x;
    const float* base = g_o + (size_t)b*SS*DD + g*128;

    float s = 0.f, ss = 0.f;
    #pragma unroll
    for (int it = 0; it < 8; ++it) {
        int idx = tid + it*256;          // 0..2047 (64 rows x 32 float4)
        int r = idx >> 5, c4 = (idx & 31) << 2;
        float4 v = *(const float4*)&base[(size_t)(r0 + r)*DD + c4];
        s  += v.x + v.y + v.z + v.w;
        ss += v.x*v.x + v.y*v.y + v.z*v.z + v.w*v.w;
    }
    __shared__ float rs[256], rq[256];
    rs[tid] = s; rq[tid] = ss;
    __syncthreads();
    for (int off = 128; off > 0; off >>= 1) {
        if (tid < off) { rs[tid] += rs[tid+off]; rq[tid] += rq[tid+off]; }
        __syncthreads();
    }
    if (tid == 0) {
        g_part_s[gi*32 + blockIdx.x] = rs[0];
        g_part_q[gi*32 + blockIdx.x] = rq[0];
    }
}

// ============================================================
// Kernel 3b: stats stage 2 (deterministic serial over 32 partials)
// ============================================================
__global__ __launch_bounds__(32) void gn_stats2_kernel()
{
    int gi = threadIdx.x;
    if (gi >= BB*GG) return;
    float s = 0.f, q = 0.f;
    #pragma unroll
    for (int i = 0; i < 32; ++i) {
        s += g_part_s[gi*32 + i];
        q += g_part_q[gi*32 + i];
    }
    const float n = (float)(SS*128);
    float mu  = s / n;
    float var = q / n - mu*mu;
    g_mu[gi]   = mu;
    g_rstd[gi] = rsqrtf(var + 1e-5f);
}

// ============================================================
// Kernel 3c: apply GroupNorm and split to bf16 hi/lo
// ============================================================
__global__ __launch_bounds__(256) void gn_apply_kernel(
    const float* __restrict__ gw, const float* __restrict__ gb)
{
    int i = (blockIdx.x * 256 + threadIdx.x) * 4;
    if (i >= NROW*DD) return;
    int row = i >> 9, col = i & 511;
    int gi = (row >> 11)*4 + (col >> 7);
    float mu = g_mu[gi], rst = g_rstd[gi];
    float4 a = *(const float4*)&g_o[i];
    float4 w = *(const float4*)&gw[col];
    float4 s = *(const float4*)&gb[col];
    split1((a.x - mu)*rst*w.x + s.x, g_oh[i+0], g_ol[i+0]);
    split1((a.y - mu)*rst*w.y + s.y, g_oh[i+1], g_ol[i+1]);
    split1((a.z - mu)*rst*w.z + s.z, g_oh[i+2], g_ol[i+2]);
    split1((a.w - mu)*rst*w.w + s.w, g_oh[i+3], g_ol[i+3]);
}

// ============================================================
// Kernel 4: output GEMM (bf16x3 mma), y = norm(o) @ out_w^T + b
// ============================================================
__global__ __launch_bounds__(128) void out_mma_kernel(
    const float* __restrict__ bias, float* __restrict__ y)
{
    __shared__ __nv_bfloat16 Ah[64*SR], Al[64*SR], Bh[64*SR], Bl[64*SR];

    const int tid = threadIdx.x, lane = tid & 31, warp = tid >> 5;
    const int m0 = blockIdx.x * 64, n0 = blockIdx.y * 64;

    const __nv_bfloat16* Wh = g_wh + (size_t)5*DD*DD;
    const __nv_bfloat16* Wl = g_wl + (size_t)5*DD*DD;

    float c[8][4] = {};

    const unsigned ah_b = smem_u32(Ah), al_b = smem_u32(Al);
    const unsigned bh_b = smem_u32(Bh), bl_b = smem_u32(Bl);
    const int arow   = warp*16 + (lane & 7) + ((lane >> 3) & 1) * 8;
    const int acol   = ((lane >> 4) << 3);
    const int browin = (lane & 7) + ((lane >> 4) << 3);
    const int bcol   = (((lane >> 3) & 1) << 3);

    for (int k0 = 0; k0 < DD; k0 += 64) {
        #pragma unroll
        for (int it = 0; it < 4; ++it) {
            int idx = tid + it*128;
            int row = idx >> 3, c8 = (idx & 7) << 3;
            size_t ga = (size_t)(m0+row)*DD + k0 + c8;
            size_t gb = (size_t)(n0+row)*DD + k0 + c8;
            *(uint4*)&Ah[row*SR+c8] = *(const uint4*)&g_oh[ga];
            *(uint4*)&Al[row*SR+c8] = *(const uint4*)&g_ol[ga];
            *(uint4*)&Bh[row*SR+c8] = *(const uint4*)&Wh[gb];
            *(uint4*)&Bl[row*SR+c8] = *(const uint4*)&Wl[gb];
        }
        __syncthreads();
        mma_tile64(c, ah_b, al_b, bh_b, bl_b, arow, acol, browin, bcol);
        __syncthreads();
    }

    const int gid = lane >> 2, tig = lane & 3;
    #pragma unroll
    for (int nf = 0; nf < 8; ++nf)
        #pragma unroll
        for (int hf = 0; hf < 2; ++hf) {
            int r = m0 + warp*16 + gid + hf*8;
            int n = n0 + nf*8 + tig*2;
            float2 o;
            o.x = c[nf][2*hf]   + bias[n];
            o.y = c[nf][2*hf+1] + bias[n+1];
            *(float2*)&y[(size_t)r*DD + n] = o;
        }
}

// ============================================================
// launch
// ============================================================
extern "C" void kernel_launch(void* const* d_in, const int* in_sizes, int n_in,
                              void* d_out, int out_size)
{
    const float* x   = (const float*)d_in[0];
    const float* K1w = (const float*)d_in[1];
    const float* K1b = (const float*)d_in[2];
    const float* Q1w = (const float*)d_in[3];
    const float* K2w = (const float*)d_in[4];
    const float* K2b = (const float*)d_in[5];
    const float* Q2w = (const float*)d_in[6];
    const float* Vw  = (const float*)d_in[7];
    const float* lq1 = (const float*)d_in[8];
    const float* lk1 = (const float*)d_in[9];
    const float* lq2 = (const float*)d_in[10];
    const float* lk2 = (const float*)d_in[11];
    const float* gw  = (const float*)d_in[12];
    const float* gb  = (const float*)d_in[13];
    const float* Ow  = (const float*)d_in[14];
    const float* Ob  = (const float*)d_in[15];
    float* y = (float*)d_out;

    const int ATT_SMEM = 10 * 64 * SR * (int)sizeof(__nv_bfloat16);  // 92160 B
    cudaFuncSetAttribute(attn_mma_kernel,
                         cudaFuncAttributeMaxDynamicSharedMemorySize, ATT_SMEM);

    const int NSPLIT = (NROW*DD/4 + 6*DD*DD/4 + 255) / 256;
    split_inputs_kernel<<<NSPLIT, 256>>>(x, Q1w, K1w, Q2w, K2w, Vw, Ow);
    qkv_mma_kernel<<<dim3(NROW/64, DD/64, 5), 128>>>(K1b, K2b);
    attn_mma_kernel<<<dim3(SS/64, BB*HH), 128, ATT_SMEM>>>(lq1, lk1, lq2, lk2);
    gn_stats1_kernel<<<dim3(32, BB*GG), 256>>>();
    gn_stats2_kernel<<<1, 32>>>();
    gn_apply_kernel<<<NROW*DD/4/256, 256>>>(gw, gb);
    out_mma_kernel<<<dim3(NROW/64, DD/64), 128>>>(Ob, y);
}